// round 3
// baseline (speedup 1.0000x reference)
#include <cuda_runtime.h>
#include <cuda_bf16.h>
#include <cstdint>
#include <cstddef>

// TMPNN: 7 steps of x += poly(x) @ W, M=131072, N=32.
// Symmetric fold: K = 528 (upper-tri monomials) + 32 linear + 1 bias = 561 -> 576.
// Per-CTA persistent 128-row tile; P built bf16 in SMEM; classic HMMA
// (mma.sync.m16n8k16 bf16, fp32 accum) since compute_100 PTX lacks tcgen05.

namespace {

constexpr int N_STEPS = 7;
constexpr int NKT     = 36;            // k-tiles of 16 -> K_mma = 576
constexpr int PSTR    = 584;           // P row stride in elements (576 + 8 pad)
constexpr int K_HALF  = 288;           // producer split point (multiple of 8)

// SMEM layout (byte offsets into dynamic smem)
constexpr int OFF_X  = 0;                       // float xs[128][33]
constexpr int OFF_P  = 16896;                   // bf16 P[128][584]
constexpr int OFF_BF = OFF_P + 128 * PSTR * 2;  // 166400: uint2 Bf[4][36][32]
constexpr int SMEM_BYTES = OFF_BF + 4 * NKT * 32 * 8;   // 203264

__device__ __forceinline__ uint32_t cvta_smem(const void* p) {
    uint32_t a;
    asm volatile("{\n\t.reg .u64 t;\n\tcvta.to.shared.u64 t, %1;\n\tcvt.u32.u64 %0, t;\n\t}"
                 : "=r"(a) : "l"(p));
    return a;
}

__device__ __forceinline__ uint32_t pack2(float lo, float hi) {
    uint32_t r;
    asm("cvt.rn.bf16x2.f32 %0, %1, %2;" : "=r"(r) : "f"(hi), "f"(lo));
    return r;
}

__device__ __forceinline__ void sts128(uint32_t a, uint32_t x, uint32_t y,
                                       uint32_t z, uint32_t w) {
    asm volatile("st.shared.v4.b32 [%0], {%1,%2,%3,%4};"
                 :: "r"(a), "r"(x), "r"(y), "r"(z), "r"(w));
}

__device__ __forceinline__ void ldmA(uint32_t& a0, uint32_t& a1, uint32_t& a2,
                                     uint32_t& a3, uint32_t addr) {
    asm volatile("ldmatrix.sync.aligned.m8n8.x4.shared.b16 {%0,%1,%2,%3}, [%4];"
                 : "=r"(a0), "=r"(a1), "=r"(a2), "=r"(a3) : "r"(addr));
}

__device__ __forceinline__ void mma16816(float* c, uint32_t a0, uint32_t a1,
                                         uint32_t a2, uint32_t a3,
                                         uint32_t b0, uint32_t b1) {
    asm volatile("mma.sync.aligned.m16n8k16.row.col.f32.bf16.bf16.f32 "
                 "{%0,%1,%2,%3}, {%4,%5,%6,%7}, {%8,%9}, {%0,%1,%2,%3};"
                 : "+f"(c[0]), "+f"(c[1]), "+f"(c[2]), "+f"(c[3])
                 : "r"(a0), "r"(a1), "r"(a2), "r"(a3), "r"(b0), "r"(b1));
}

// Symmetric-folded weight value for monomial column k, output feature n.
// k<528: upper-tri pair; 528..559: linear; 560: bias; >=561: zero pad.
__device__ float wv(const float* __restrict__ W, int k, int n) {
    if (k < 528) {
        int f = 0;
        #pragma unroll 1
        while (f < 31 && (32 * (f + 1) - ((f + 1) * f) / 2) <= k) ++f;
        const int base = 32 * f - (f * (f - 1)) / 2;
        const int m = f + (k - base);
        float w = W[(33 + f * 32 + m) * 32 + n];
        if (m != f) w += W[(33 + m * 32 + f) * 32 + n];
        return w;
    }
    if (k < 560) return W[(1 + (k - 528)) * 32 + n];
    if (k == 560) return W[n];
    return 0.0f;
}

// Build monomial columns [K0, K1) of this thread's row into P (bf16 pairs,
// STS.128 every 8 columns). All k are static after unrolling.
#define EMIT(kc, vexpr)                                                        \
    do {                                                                       \
        const int _k = (kc);                                                   \
        if (_k >= K0 && _k < K1) {                                             \
            const float _v = (vexpr);                                          \
            if ((_k & 1) == 0) lo = _v;                                        \
            else {                                                             \
                const uint32_t _pr = pack2(lo, _v);                            \
                switch ((_k >> 1) & 3) {                                       \
                    case 0: st0 = _pr; break;                                  \
                    case 1: st1 = _pr; break;                                  \
                    case 2: st2 = _pr; break;                                  \
                    default: st3 = _pr; break;                                 \
                }                                                              \
                if ((_k & 7) == 7)                                             \
                    sts128(pb + (uint32_t)((_k & ~7) * 2), st0, st1, st2, st3);\
            }                                                                  \
        }                                                                      \
    } while (0)

template <int K0, int K1>
__device__ __forceinline__ void build_range(const float xr[32], uint32_t pb) {
    float lo = 0.0f;
    uint32_t st0 = 0, st1 = 0, st2 = 0, st3 = 0;
    #pragma unroll
    for (int f = 0; f < 32; ++f) {
        const int kb = 32 * f - (f * (f - 1)) / 2;
        #pragma unroll
        for (int m = f; m < 32; ++m) EMIT(kb + (m - f), xr[f] * xr[m]);
    }
    #pragma unroll
    for (int j = 0; j < 32; ++j) EMIT(528 + j, xr[j]);
    EMIT(560, 1.0f);
    #pragma unroll
    for (int j = 561; j < PSTR; ++j) EMIT(j, 0.0f);
}

} // namespace

__global__ void __launch_bounds__(256, 1)
tmpnn_kernel(const float* __restrict__ X, const float* __restrict__ W,
             float* __restrict__ out)
{
    extern __shared__ char smem[];
    float* xs = reinterpret_cast<float*>(smem + OFF_X);          // [128][33]
    uint2* Bf = reinterpret_cast<uint2*>(smem + OFF_BF);         // [4][36][32]
    const uint32_t sbase = cvta_smem(smem);
    const uint32_t pP = sbase + OFF_P;

    const int tid  = threadIdx.x;
    const int lane = tid & 31;
    const int w    = tid >> 5;

    // ---- stage X tile (coalesced gmem -> padded smem) ----
    const float* Xb = X + (size_t)blockIdx.x * 4096;
    for (int i = tid; i < 4096; i += 256)
        xs[(i >> 5) * 33 + (i & 31)] = Xb[i];

    // ---- build frag-ordered symmetric-folded B table (once per CTA) ----
    // Bf[nt][ki][l]: b0 = {B[kb][n], B[kb+1][n]}, b1 = {B[kb+8][n], B[kb+9][n]}
    for (int idx = tid; idx < 4 * NKT * 32; idx += 256) {
        const int nt = idx / (NKT * 32);
        const int rem = idx - nt * NKT * 32;
        const int ki = rem >> 5;
        const int l  = rem & 31;
        const int n  = nt * 8 + (l >> 2);
        const int kb = ki * 16 + (l & 3) * 2;
        const float v0 = wv(W, kb, n),     v1 = wv(W, kb + 1, n);
        const float v2 = wv(W, kb + 8, n), v3 = wv(W, kb + 9, n);
        Bf[idx] = make_uint2(pack2(v0, v1), pack2(v2, v3));
    }
    __syncthreads();

    // A-frag ldmatrix addressing (per lane, fixed across k-tiles)
    const uint32_t arow  = (uint32_t)(w * 16 + (lane & 7) + ((lane >> 3) & 1) * 8);
    const uint32_t acolh = (uint32_t)((lane >> 4) * 8);
    const uint32_t abase = pP + arow * (PSTR * 2) + acolh * 2;

    for (int step = 0; step < N_STEPS; ++step) {
        // ---- build P: 2 threads per row, static-unrolled monomials ----
        {
            const int row = tid & 127;
            float xr[32];
            #pragma unroll
            for (int j = 0; j < 32; ++j) xr[j] = xs[row * 33 + j];
            const uint32_t pb = pP + (uint32_t)row * (PSTR * 2);
            if ((tid >> 7) == 0) build_range<0, K_HALF>(xr, pb);
            else                 build_range<K_HALF, PSTR>(xr, pb);
        }
        __syncthreads();

        // ---- HMMA: warp w owns rows [16w, 16w+16), all 32 outputs ----
        float acc[4][4];
        #pragma unroll
        for (int nt = 0; nt < 4; ++nt)
            #pragma unroll
            for (int i = 0; i < 4; ++i) acc[nt][i] = 0.0f;

        #pragma unroll 4
        for (int ki = 0; ki < NKT; ++ki) {
            uint32_t a0, a1, a2, a3;
            ldmA(a0, a1, a2, a3, abase + (uint32_t)(ki * 32));
            #pragma unroll
            for (int nt = 0; nt < 4; ++nt) {
                const uint2 b = Bf[nt * (NKT * 32) + ki * 32 + lane];
                mma16816(acc[nt], a0, a1, a2, a3, b.x, b.y);
            }
        }

        // ---- epilogue: residual add into xs (each element owned uniquely) ----
        {
            const int r0 = w * 16 + (lane >> 2);
            const int cb = (lane & 3) * 2;
            #pragma unroll
            for (int nt = 0; nt < 4; ++nt) {
                const int c = nt * 8 + cb;
                xs[r0 * 33 + c]           += acc[nt][0];
                xs[r0 * 33 + c + 1]       += acc[nt][1];
                xs[(r0 + 8) * 33 + c]     += acc[nt][2];
                xs[(r0 + 8) * 33 + c + 1] += acc[nt][3];
            }
        }
        __syncthreads();
    }

    if (tid < 128)
        out[(size_t)blockIdx.x * 128 + tid] = xs[tid * 33];
}

extern "C" void kernel_launch(void* const* d_in, const int* in_sizes, int n_in,
                              void* d_out, int out_size) {
    const float* X = (const float*)d_in[0];
    const float* W = (const float*)d_in[1];
    float* out = (float*)d_out;
    const int rows = in_sizes[0] / 32;
    const int blocks = rows / 128;
    cudaFuncSetAttribute(tmpnn_kernel, cudaFuncAttributeMaxDynamicSharedMemorySize,
                         SMEM_BYTES);
    tmpnn_kernel<<<blocks, 256, SMEM_BYTES>>>(X, W, out);
}

// round 4
// speedup vs baseline: 1.2571x; 1.2571x over previous
#include <cuda_runtime.h>
#include <cuda_bf16.h>
#include <cstdint>
#include <cstddef>

// TMPNN: 7 steps of x += poly(x) @ W, M=131072, N=32, symmetric-folded K=561->576.
// R4: K-chunked (6 x 96) double-buffered P so SMEM = 104.5 KB -> 2 CTAs/SM;
// B-fragments preloaded to frag-ordered uint4 table (2 x LDS.128 per k-tile).

namespace {

constexpr int N_STEPS = 7;
constexpr int NKT   = 36;            // total k-tiles of 16 (K = 576)
constexpr int NCH   = 6;             // K chunks
constexpr int KT_CH = 6;             // k-tiles per chunk
constexpr int CHK   = 96;            // cols per chunk
constexpr int PSTR  = 104;           // P chunk row stride (elements); 208B rows, ldmatrix conflict-free
constexpr int PBUF  = 128 * PSTR * 2;            // 26624 B per buffer

constexpr int OFF_X  = 0;                        // float xs[128][33] = 16896
constexpr int OFF_P  = 128 * 33 * 4;             // 16896: 2 P buffers
constexpr int OFF_BF = OFF_P + 2 * PBUF;         // 70144: uint4 Bf4[36][32][2]
constexpr int SMEM_BYTES = OFF_BF + NKT * 32 * 2 * 16;   // 107008

__device__ __forceinline__ uint32_t cvta_smem(const void* p) {
    uint32_t a;
    asm volatile("{\n\t.reg .u64 t;\n\tcvta.to.shared.u64 t, %1;\n\tcvt.u32.u64 %0, t;\n\t}"
                 : "=r"(a) : "l"(p));
    return a;
}

__device__ __forceinline__ uint32_t pack2(float lo, float hi) {
    uint32_t r;
    asm("cvt.rn.bf16x2.f32 %0, %1, %2;" : "=r"(r) : "f"(hi), "f"(lo));
    return r;
}

__device__ __forceinline__ void sts128(uint32_t a, uint32_t x, uint32_t y,
                                       uint32_t z, uint32_t w) {
    asm volatile("st.shared.v4.b32 [%0], {%1,%2,%3,%4};"
                 :: "r"(a), "r"(x), "r"(y), "r"(z), "r"(w));
}

__device__ __forceinline__ void ldmA(uint32_t& a0, uint32_t& a1, uint32_t& a2,
                                     uint32_t& a3, uint32_t addr) {
    asm volatile("ldmatrix.sync.aligned.m8n8.x4.shared.b16 {%0,%1,%2,%3}, [%4];"
                 : "=r"(a0), "=r"(a1), "=r"(a2), "=r"(a3) : "r"(addr));
}

__device__ __forceinline__ void mma16816(float* c, uint32_t a0, uint32_t a1,
                                         uint32_t a2, uint32_t a3,
                                         uint32_t b0, uint32_t b1) {
    asm volatile("mma.sync.aligned.m16n8k16.row.col.f32.bf16.bf16.f32 "
                 "{%0,%1,%2,%3}, {%4,%5,%6,%7}, {%8,%9}, {%0,%1,%2,%3};"
                 : "+f"(c[0]), "+f"(c[1]), "+f"(c[2]), "+f"(c[3])
                 : "r"(a0), "r"(a1), "r"(a2), "r"(a3), "r"(b0), "r"(b1));
}

// Symmetric-folded weight: col k, output n.
// k<528: upper-tri pair; 528..559: linear; 560: bias; >=561: zero pad.
__device__ float wv(const float* __restrict__ W, int k, int n) {
    if (k < 528) {
        int f = 0;
        #pragma unroll 1
        while (f < 31 && (32 * (f + 1) - ((f + 1) * f) / 2) <= k) ++f;
        const int base = 32 * f - (f * (f - 1)) / 2;
        const int m = f + (k - base);
        float w = __ldg(&W[(33 + f * 32 + m) * 32 + n]);
        if (m != f) w += __ldg(&W[(33 + m * 32 + f) * 32 + n]);
        return w;
    }
    if (k < 560) return __ldg(&W[(1 + (k - 528)) * 32 + n]);
    if (k == 560) return __ldg(&W[n]);
    return 0.0f;
}

// Emit monomial column k (static after unroll) if inside this builder's
// 48-col span [K0, K0+48); store offset is chunk-local ((k - KB)*2 bytes).
#define EMIT(kc, vexpr)                                                          \
    do {                                                                         \
        const int _k = (kc);                                                     \
        if (_k >= K0 && _k < K0 + 48) {                                          \
            const float _v = (vexpr);                                            \
            if ((_k & 1) == 0) lo = _v;                                          \
            else {                                                               \
                const uint32_t _pr = pack2(lo, _v);                              \
                switch ((_k >> 1) & 3) {                                         \
                    case 0: st0 = _pr; break;                                    \
                    case 1: st1 = _pr; break;                                    \
                    case 2: st2 = _pr; break;                                    \
                    default: st3 = _pr; break;                                   \
                }                                                                \
                if ((_k & 7) == 7)                                               \
                    sts128(pb + (uint32_t)(((_k & ~7) - KB) * 2),                \
                           st0, st1, st2, st3);                                  \
            }                                                                    \
        }                                                                        \
    } while (0)

template <int K0>
__device__ __forceinline__ void build48(const float xr[32], uint32_t pb) {
    constexpr int KB = (K0 / CHK) * CHK;
    float lo = 0.0f;
    uint32_t st0 = 0, st1 = 0, st2 = 0, st3 = 0;
    #pragma unroll
    for (int f = 0; f < 32; ++f) {
        const int kb = 32 * f - (f * (f - 1)) / 2;
        #pragma unroll
        for (int m = f; m < 32; ++m) EMIT(kb + (m - f), xr[f] * xr[m]);
    }
    #pragma unroll
    for (int j = 0; j < 32; ++j) EMIT(528 + j, xr[j]);
    EMIT(560, 1.0f);
    #pragma unroll
    for (int j = 561; j < 576; ++j) EMIT(j, 0.0f);
}

// c is compile-time after the unrolled chunk loop; h is a uniform runtime bit.
template <int C>
__device__ __forceinline__ void build_chunk(int h, const float xr[32], uint32_t pb) {
    if (h == 0) build48<C * CHK>(xr, pb);
    else        build48<C * CHK + 48>(xr, pb);
}

} // namespace

__global__ void __launch_bounds__(256, 2)
tmpnn_kernel(const float* __restrict__ X, const float* __restrict__ W,
             float* __restrict__ out)
{
    extern __shared__ char smem[];
    float* xs  = reinterpret_cast<float*>(smem + OFF_X);      // [128][33]
    uint4* Bf4 = reinterpret_cast<uint4*>(smem + OFF_BF);     // [36][32][2]
    const uint32_t sbase = cvta_smem(smem);

    const int tid  = threadIdx.x;
    const int lane = tid & 31;
    const int w    = tid >> 5;
    const int row  = tid & 127;        // build row
    const int h    = tid >> 7;         // build half (0: cols [0,48), 1: [48,96) of chunk)

    // ---- stage X tile ----
    const float* Xb = X + (size_t)blockIdx.x * 4096;
    for (int i = tid; i < 4096; i += 256)
        xs[(i >> 5) * 33 + (i & 31)] = Xb[i];

    // ---- frag-ordered symmetric-folded B table (once per CTA) ----
    // Bf4[kt][l][p]: nt pair {2p, 2p+1}; fields = {b0(n0),b1(n0),b0(n0+8),b1(n0+8)}
    for (int idx = tid; idx < NKT * 64; idx += 256) {
        const int kt = idx >> 6, rem = idx & 63;
        const int l = rem >> 1, p = rem & 1;
        const int n0 = p * 16 + (l >> 2);
        const int kb = kt * 16 + (l & 3) * 2;
        uint4 q;
        q.x = pack2(wv(W, kb, n0),     wv(W, kb + 1, n0));
        q.y = pack2(wv(W, kb + 8, n0), wv(W, kb + 9, n0));
        q.z = pack2(wv(W, kb, n0 + 8),     wv(W, kb + 1, n0 + 8));
        q.w = pack2(wv(W, kb + 8, n0 + 8), wv(W, kb + 9, n0 + 8));
        Bf4[idx] = q;
    }
    __syncthreads();

    const uint32_t pP     = sbase + OFF_P;
    const uint32_t arow   = (uint32_t)(w * 16 + (lane & 15));
    const uint32_t acol2  = (uint32_t)((lane >> 4) * 16);     // byte offset of 8-col half
    const uint32_t pbrow  = (uint32_t)row * (PSTR * 2);

    for (int step = 0; step < N_STEPS; ++step) {
        float xr[32];
        #pragma unroll
        for (int j = 0; j < 32; ++j) xr[j] = xs[row * 33 + j];

        float acc[4][4];
        #pragma unroll
        for (int nt = 0; nt < 4; ++nt)
            #pragma unroll
            for (int i = 0; i < 4; ++i) acc[nt][i] = 0.0f;

        #pragma unroll
        for (int c = 0; c < NCH; ++c) {
            const uint32_t pbuf = pP + (uint32_t)(c & 1) * PBUF;

            switch (c) {     // folds: c is constant in the unrolled loop
                case 0: build_chunk<0>(h, xr, pbuf + pbrow); break;
                case 1: build_chunk<1>(h, xr, pbuf + pbrow); break;
                case 2: build_chunk<2>(h, xr, pbuf + pbrow); break;
                case 3: build_chunk<3>(h, xr, pbuf + pbrow); break;
                case 4: build_chunk<4>(h, xr, pbuf + pbrow); break;
                default: build_chunk<5>(h, xr, pbuf + pbrow); break;
            }
            __syncthreads();

            const uint32_t ab = pbuf + arow * (PSTR * 2) + acol2;
            #pragma unroll
            for (int ki = 0; ki < KT_CH; ++ki) {
                uint32_t a0, a1, a2, a3;
                ldmA(a0, a1, a2, a3, ab + (uint32_t)(ki * 32));
                const int kt = c * KT_CH + ki;
                const uint4 qa = Bf4[kt * 64 + lane * 2 + 0];
                const uint4 qb = Bf4[kt * 64 + lane * 2 + 1];
                mma16816(acc[0], a0, a1, a2, a3, qa.x, qa.y);
                mma16816(acc[1], a0, a1, a2, a3, qa.z, qa.w);
                mma16816(acc[2], a0, a1, a2, a3, qb.x, qb.y);
                mma16816(acc[3], a0, a1, a2, a3, qb.z, qb.w);
            }
        }

        // ---- epilogue: residual add into xs (exclusive per-element ownership) ----
        {
            const int r0 = w * 16 + (lane >> 2);
            const int cb = (lane & 3) * 2;
            #pragma unroll
            for (int nt = 0; nt < 4; ++nt) {
                const int cc = nt * 8 + cb;
                xs[r0 * 33 + cc]           += acc[nt][0];
                xs[r0 * 33 + cc + 1]       += acc[nt][1];
                xs[(r0 + 8) * 33 + cc]     += acc[nt][2];
                xs[(r0 + 8) * 33 + cc + 1] += acc[nt][3];
            }
        }
        __syncthreads();
    }

    if (tid < 128)
        out[(size_t)blockIdx.x * 128 + tid] = xs[tid * 33];
}

extern "C" void kernel_launch(void* const* d_in, const int* in_sizes, int n_in,
                              void* d_out, int out_size) {
    const float* X = (const float*)d_in[0];
    const float* W = (const float*)d_in[1];
    float* out = (float*)d_out;
    const int rows = in_sizes[0] / 32;
    const int blocks = rows / 128;
    cudaFuncSetAttribute(tmpnn_kernel, cudaFuncAttributeMaxDynamicSharedMemorySize,
                         SMEM_BYTES);
    tmpnn_kernel<<<blocks, 256, SMEM_BYTES>>>(X, W, out);
}

// round 5
// speedup vs baseline: 1.4422x; 1.1472x over previous
#include <cuda_runtime.h>
#include <cuda_bf16.h>
#include <cstdint>
#include <cstddef>

// TMPNN: 7 steps of x += poly(x) @ W, M=131072, N=32, symmetric-folded K=561->576.
// R5: warp-autonomous steps (warp builds the rows it MMAs -> zero __syncthreads
// in the main loop), single P buffer, lane-contiguous B-frag tables, last-step
// N-thinning (only output col 0 needed).

namespace {

constexpr int N_STEPS = 7;
constexpr int NKT   = 36;            // k-tiles of 16 (K = 576)
constexpr int NCH   = 6;             // K chunks
constexpr int KT_CH = 6;             // k-tiles per chunk
constexpr int CHK   = 96;            // cols per chunk
constexpr int PSTR  = 104;           // P row stride els (208 B; ldmatrix conflict-free)
constexpr int XSTR  = 34;            // xs row stride (136 B, 8B-aligned rows)

constexpr int OFF_X  = 0;                          // float xs[128][34] = 17408
constexpr int OFF_P  = 128 * XSTR * 4;             // 17408: bf16 P[128][104] = 26624
constexpr int OFF_BL = OFF_P + 128 * PSTR * 2;     // 44032: uint4 BfLo[36][32] = 18432
constexpr int OFF_BH = OFF_BL + NKT * 32 * 16;     // 62464: uint4 BfHi[36][32]
constexpr int SMEM_BYTES = OFF_BH + NKT * 32 * 16; // 80896  -> 2 CTAs/SM

__device__ __forceinline__ uint32_t cvta_smem(const void* p) {
    uint32_t a;
    asm volatile("{\n\t.reg .u64 t;\n\tcvta.to.shared.u64 t, %1;\n\tcvt.u32.u64 %0, t;\n\t}"
                 : "=r"(a) : "l"(p));
    return a;
}

__device__ __forceinline__ uint32_t pack2(float lo, float hi) {
    uint32_t r;
    asm("cvt.rn.bf16x2.f32 %0, %1, %2;" : "=r"(r) : "f"(hi), "f"(lo));
    return r;
}

__device__ __forceinline__ void sts128(uint32_t a, uint32_t x, uint32_t y,
                                       uint32_t z, uint32_t w) {
    asm volatile("st.shared.v4.b32 [%0], {%1,%2,%3,%4};"
                 :: "r"(a), "r"(x), "r"(y), "r"(z), "r"(w));
}

__device__ __forceinline__ void ldmA(uint32_t& a0, uint32_t& a1, uint32_t& a2,
                                     uint32_t& a3, uint32_t addr) {
    asm volatile("ldmatrix.sync.aligned.m8n8.x4.shared.b16 {%0,%1,%2,%3}, [%4];"
                 : "=r"(a0), "=r"(a1), "=r"(a2), "=r"(a3) : "r"(addr));
}

__device__ __forceinline__ void mma16816(float* c, uint32_t a0, uint32_t a1,
                                         uint32_t a2, uint32_t a3,
                                         uint32_t b0, uint32_t b1) {
    asm volatile("mma.sync.aligned.m16n8k16.row.col.f32.bf16.bf16.f32 "
                 "{%0,%1,%2,%3}, {%4,%5,%6,%7}, {%8,%9}, {%0,%1,%2,%3};"
                 : "+f"(c[0]), "+f"(c[1]), "+f"(c[2]), "+f"(c[3])
                 : "r"(a0), "r"(a1), "r"(a2), "r"(a3), "r"(b0), "r"(b1));
}

// Symmetric-folded weight: monomial col k, output n.
// k<528: upper-tri pair; 528..559: linear; 560: bias; >=561: zero pad.
__device__ float wv(const float* __restrict__ W, int k, int n) {
    if (k < 528) {
        int f = 0;
        #pragma unroll 1
        while (f < 31 && (32 * (f + 1) - ((f + 1) * f) / 2) <= k) ++f;
        const int base = 32 * f - (f * (f - 1)) / 2;
        const int m = f + (k - base);
        float w = __ldg(&W[(33 + f * 32 + m) * 32 + n]);
        if (m != f) w += __ldg(&W[(33 + m * 32 + f) * 32 + n]);
        return w;
    }
    if (k < 560) return __ldg(&W[(1 + (k - 528)) * 32 + n]);
    if (k == 560) return __ldg(&W[n]);
    return 0.0f;
}

// Emit monomial col k (compile-time after unroll) if in [K0, K0+48);
// store offset chunk-local: (k - KB)*2 bytes.
#define EMIT(kc, vexpr)                                                          \
    do {                                                                         \
        const int _k = (kc);                                                     \
        if (_k >= K0 && _k < K0 + 48) {                                          \
            const float _v = (vexpr);                                            \
            if ((_k & 1) == 0) lo = _v;                                          \
            else {                                                               \
                const uint32_t _pr = pack2(lo, _v);                              \
                switch ((_k >> 1) & 3) {                                         \
                    case 0: st0 = _pr; break;                                    \
                    case 1: st1 = _pr; break;                                    \
                    case 2: st2 = _pr; break;                                    \
                    default: st3 = _pr; break;                                   \
                }                                                                \
                if ((_k & 7) == 7)                                               \
                    sts128(pb + (uint32_t)(((_k & ~7) - KB) * 2),                \
                           st0, st1, st2, st3);                                  \
            }                                                                    \
        }                                                                        \
    } while (0)

template <int K0>
__device__ __forceinline__ void build48(const float xr[32], uint32_t pb) {
    constexpr int KB = (K0 / CHK) * CHK;
    float lo = 0.0f;
    uint32_t st0 = 0, st1 = 0, st2 = 0, st3 = 0;
    #pragma unroll
    for (int f = 0; f < 32; ++f) {
        const int kb = 32 * f - (f * (f - 1)) / 2;
        #pragma unroll
        for (int m = f; m < 32; ++m) EMIT(kb + (m - f), xr[f] * xr[m]);
    }
    #pragma unroll
    for (int j = 0; j < 32; ++j) EMIT(528 + j, xr[j]);
    EMIT(560, 1.0f);
    #pragma unroll
    for (int j = 561; j < 576; ++j) EMIT(j, 0.0f);
}

template <int C>
__device__ __forceinline__ void build_chunk(int h, const float xr[32], uint32_t pb) {
    if (h == 0) build48<C * CHK>(xr, pb);
    else        build48<C * CHK + 48>(xr, pb);
}

} // namespace

__global__ void __launch_bounds__(256, 2)
tmpnn_kernel(const float* __restrict__ X, const float* __restrict__ W,
             float* __restrict__ out)
{
    extern __shared__ char smem[];
    float* xs   = reinterpret_cast<float*>(smem + OFF_X);       // [128][34]
    uint4* BfLo = reinterpret_cast<uint4*>(smem + OFF_BL);      // [36][32]
    uint4* BfHi = reinterpret_cast<uint4*>(smem + OFF_BH);      // [36][32]
    const uint32_t sbase = cvta_smem(smem);
    const uint32_t pP = sbase + OFF_P;

    const int tid  = threadIdx.x;
    const int lane = tid & 31;
    const int w    = tid >> 5;
    const int row  = w * 16 + (lane & 15);   // warp-owned build/mma row
    const int h    = lane >> 4;              // 0: cols [0,48), 1: [48,96) of chunk

    // ---- stage X tile ----
    const float* Xb = X + (size_t)blockIdx.x * 4096;
    for (int i = tid; i < 4096; i += 256)
        xs[(i >> 5) * XSTR + (i & 31)] = Xb[i];

    // ---- frag-ordered symmetric-folded B tables (lane-contiguous) ----
    // BfLo: cols n0, n0+8 (n0 = l>>2);  BfHi: cols n0+16, n0+24.
    for (int idx = tid; idx < 2 * NKT * 32; idx += 256) {
        const int t   = idx / (NKT * 32);
        const int rem = idx - t * (NKT * 32);
        const int kt  = rem >> 5;
        const int l   = rem & 31;
        const int n0  = (l >> 2) + t * 16;
        const int kb  = kt * 16 + (l & 3) * 2;
        uint4 q;
        q.x = pack2(wv(W, kb, n0),          wv(W, kb + 1, n0));
        q.y = pack2(wv(W, kb + 8, n0),      wv(W, kb + 9, n0));
        q.z = pack2(wv(W, kb, n0 + 8),      wv(W, kb + 1, n0 + 8));
        q.w = pack2(wv(W, kb + 8, n0 + 8),  wv(W, kb + 9, n0 + 8));
        (t == 0 ? BfLo : BfHi)[rem] = q;
    }
    __syncthreads();   // the only CTA-wide barrier

    const uint32_t abase = pP + (uint32_t)(w * 16 + (lane & 15)) * (PSTR * 2)
                              + (uint32_t)((lane >> 4) * 16);
    const uint32_t pbrow = pP + (uint32_t)row * (PSTR * 2);

    for (int step = 0; step < N_STEPS; ++step) {
        const bool full = (step != N_STEPS - 1);   // last step: only col 0 needed

        float xr[32];
        #pragma unroll
        for (int j = 0; j < 16; ++j) {
            const float2 v = *reinterpret_cast<const float2*>(&xs[row * XSTR + 2 * j]);
            xr[2 * j] = v.x; xr[2 * j + 1] = v.y;
        }

        float acc[4][4];
        #pragma unroll
        for (int nt = 0; nt < 4; ++nt)
            #pragma unroll
            for (int i = 0; i < 4; ++i) acc[nt][i] = 0.0f;

        #pragma unroll
        for (int c = 0; c < NCH; ++c) {
            switch (c) {
                case 0: build_chunk<0>(h, xr, pbrow); break;
                case 1: build_chunk<1>(h, xr, pbrow); break;
                case 2: build_chunk<2>(h, xr, pbrow); break;
                case 3: build_chunk<3>(h, xr, pbrow); break;
                case 4: build_chunk<4>(h, xr, pbrow); break;
                default: build_chunk<5>(h, xr, pbrow); break;
            }
            __syncwarp();   // publish this warp's P rows to its own ldmatrix

            #pragma unroll
            for (int ki = 0; ki < KT_CH; ++ki) {
                uint32_t a0, a1, a2, a3;
                ldmA(a0, a1, a2, a3, abase + (uint32_t)(ki * 32));
                const int kt = c * KT_CH + ki;
                const uint4 ql = BfLo[kt * 32 + lane];
                mma16816(acc[0], a0, a1, a2, a3, ql.x, ql.y);
                mma16816(acc[1], a0, a1, a2, a3, ql.z, ql.w);
                if (full) {
                    const uint4 qh = BfHi[kt * 32 + lane];
                    mma16816(acc[2], a0, a1, a2, a3, qh.x, qh.y);
                    mma16816(acc[3], a0, a1, a2, a3, qh.z, qh.w);
                }
            }
            __syncwarp();   // mma reads done before next chunk overwrites P
        }

        // ---- epilogue: residual add into warp-owned xs rows ----
        {
            const int r0 = w * 16 + (lane >> 2);
            const int cb = (lane & 3) * 2;
            #pragma unroll
            for (int nt = 0; nt < 4; ++nt) {
                if (nt > 0 && !full) break;
                const int cc = nt * 8 + cb;
                float2* p0 = reinterpret_cast<float2*>(&xs[r0 * XSTR + cc]);
                float2* p1 = reinterpret_cast<float2*>(&xs[(r0 + 8) * XSTR + cc]);
                float2 v0 = *p0, v1 = *p1;
                v0.x += acc[nt][0]; v0.y += acc[nt][1];
                v1.x += acc[nt][2]; v1.y += acc[nt][3];
                *p0 = v0; *p1 = v1;
            }
        }
        __syncwarp();   // epilogue visible to next step's xr reload
    }

    if (h == 0)
        out[(size_t)blockIdx.x * 128 + row] = xs[row * XSTR];
}

extern "C" void kernel_launch(void* const* d_in, const int* in_sizes, int n_in,
                              void* d_out, int out_size) {
    const float* X = (const float*)d_in[0];
    const float* W = (const float*)d_in[1];
    float* out = (float*)d_out;
    const int rows = in_sizes[0] / 32;
    const int blocks = rows / 128;
    cudaFuncSetAttribute(tmpnn_kernel, cudaFuncAttributeMaxDynamicSharedMemorySize,
                         SMEM_BYTES);
    tmpnn_kernel<<<blocks, 256, SMEM_BYTES>>>(X, W, out);
}

// round 7
// speedup vs baseline: 1.4629x; 1.0144x over previous
#include <cuda_runtime.h>
#include <cuda_bf16.h>
#include <cstdint>
#include <cstddef>

// TMPNN: 7 steps of x += poly(x) @ W, M=131072, N=32, symmetric-folded K=561->576.
// R7 (= R6 + compile fix): HMUL2 monomial build (one mul.rn.bf16x2 per column
// pair, compile-time PRMT operand combines), bf16x2 x-copy in SMEM maintained
// by the epilogue. Warp-autonomous steps, last-step N-thinning.
// Fix vs R6: column-map helpers are __host__ __device__ constexpr (harness
// nvcc lacks --expt-relaxed-constexpr).

namespace {

constexpr int N_STEPS = 7;
constexpr int NKT   = 36;            // k-tiles of 16 (K = 576)
constexpr int NCH   = 6;             // K chunks
constexpr int KT_CH = 6;             // k-tiles per chunk
constexpr int CHK   = 96;            // cols per chunk
constexpr int PSTR  = 104;           // P row stride els (208 B; ldmatrix conflict-free)
constexpr int XSTR  = 34;            // xs row stride (fp32)
constexpr int XBSTR = 20;            // xsb row stride (uint32 bf16x2), 80 B

constexpr int OFF_X  = 0;                           // float xs[128][34] = 17408
constexpr int OFF_XB = 128 * XSTR * 4;              // 17408: u32 xsb[128][20] = 10240
constexpr int OFF_P  = OFF_XB + 128 * XBSTR * 4;    // 27648: bf16 P[128][104] = 26624
constexpr int OFF_BL = OFF_P + 128 * PSTR * 2;      // 54272: uint4 BfLo[36][32] = 18432
constexpr int OFF_BH = OFF_BL + NKT * 32 * 16;      // 72704: uint4 BfHi[36][32]
constexpr int SMEM_BYTES = OFF_BH + NKT * 32 * 16;  // 91136 -> 2 CTAs/SM

__device__ __forceinline__ uint32_t cvta_smem(const void* p) {
    uint32_t a;
    asm volatile("{\n\t.reg .u64 t;\n\tcvta.to.shared.u64 t, %1;\n\tcvt.u32.u64 %0, t;\n\t}"
                 : "=r"(a) : "l"(p));
    return a;
}

__device__ __forceinline__ uint32_t pack2(float lo, float hi) {
    uint32_t r;
    asm("cvt.rn.bf16x2.f32 %0, %1, %2;" : "=r"(r) : "f"(hi), "f"(lo));
    return r;
}

__device__ __forceinline__ void sts128(uint32_t a, uint32_t x, uint32_t y,
                                       uint32_t z, uint32_t w) {
    asm volatile("st.shared.v4.b32 [%0], {%1,%2,%3,%4};"
                 :: "r"(a), "r"(x), "r"(y), "r"(z), "r"(w));
}

__device__ __forceinline__ void ldmA(uint32_t& a0, uint32_t& a1, uint32_t& a2,
                                     uint32_t& a3, uint32_t addr) {
    asm volatile("ldmatrix.sync.aligned.m8n8.x4.shared.b16 {%0,%1,%2,%3}, [%4];"
                 : "=r"(a0), "=r"(a1), "=r"(a2), "=r"(a3) : "r"(addr));
}

__device__ __forceinline__ void mma16816(float* c, uint32_t a0, uint32_t a1,
                                         uint32_t a2, uint32_t a3,
                                         uint32_t b0, uint32_t b1) {
    asm volatile("mma.sync.aligned.m16n8k16.row.col.f32.bf16.bf16.f32 "
                 "{%0,%1,%2,%3}, {%4,%5,%6,%7}, {%8,%9}, {%0,%1,%2,%3};"
                 : "+f"(c[0]), "+f"(c[1]), "+f"(c[2]), "+f"(c[3])
                 : "r"(a0), "r"(a1), "r"(a2), "r"(a3), "r"(b0), "r"(b1));
}

// ---- symmetric-folded weight (init only) ----
__device__ float wv(const float* __restrict__ W, int k, int n) {
    if (k < 528) {
        int f = 0;
        #pragma unroll 1
        while (f < 31 && (32 * (f + 1) - ((f + 1) * f) / 2) <= k) ++f;
        const int base = 32 * f - (f * (f - 1)) / 2;
        const int m = f + (k - base);
        float w = __ldg(&W[(33 + f * 32 + m) * 32 + n]);
        if (m != f) w += __ldg(&W[(33 + m * 32 + f) * 32 + n]);
        return w;
    }
    if (k < 560) return __ldg(&W[(1 + (k - 528)) * 32 + n]);
    if (k == 560) return __ldg(&W[n]);
    return 0.0f;
}

// ---- compile-time column -> operand-half maps (host+device constexpr) ----
// col k: k<528 quad x_f*x_m (upper tri); 528..559 linear x_j; 560 bias; >560 pad.
// Half encoding: reg 0..15 = xb[reg]; 16 = ONE2 (1.0,1.0); 17 = zero.
__host__ __device__ constexpr int cfk(int k) {
    int f = 0;
    while (32 * (f + 1) - ((f + 1) * f) / 2 <= k) ++f;
    return f;
}
__host__ __device__ constexpr int cmk(int k) {
    const int f = cfk(k);
    return f + (k - (32 * f - (f * (f - 1)) / 2));
}
__host__ __device__ constexpr int uR(int k) {
    return (k < 528) ? (cfk(k) >> 1)
         : (k < 560) ? ((k - 528) >> 1)
         : (k == 560) ? 16 : 17;
}
__host__ __device__ constexpr int uH(int k) {
    return (k < 528) ? (cfk(k) & 1) : (k < 560) ? ((k - 528) & 1) : 0;
}
__host__ __device__ constexpr int vR(int k) { return (k < 528) ? (cmk(k) >> 1) : 16; }
__host__ __device__ constexpr int vH(int k) { return (k < 528) ? (cmk(k) & 1) : 0; }

// Combine two bf16 halves into one bf16x2 register (PRMT, sel folded).
template <int R0, int H0, int R1, int H1>
__device__ __forceinline__ uint32_t comb(const uint32_t* xb, uint32_t ONE2) {
    const uint32_t s0 = (R0 >= 16) ? ((R0 == 16) ? ONE2 : 0u) : xb[(R0 < 16) ? R0 : 0];
    const uint32_t s1 = (R1 >= 16) ? ((R1 == 16) ? ONE2 : 0u) : xb[(R1 < 16) ? R1 : 0];
    if (R0 == R1 && H0 == 0 && H1 == 1) return s0;          // natural pair
    const int sel = (H0 ? 0x32 : 0x10) | ((H1 ? 0x76 : 0x54) << 8);
    return __byte_perm(s0, s1, sel);
}

// One bf16x2 = values of columns {A, A+1}.
template <int A>
__device__ __forceinline__ uint32_t pair_val(const uint32_t* xb, uint32_t ONE2) {
    const uint32_t u = comb<uR(A), uH(A), uR(A + 1), uH(A + 1)>(xb, ONE2);
    const uint32_t v = comb<vR(A), vH(A), vR(A + 1), vH(A + 1)>(xb, ONE2);
    uint32_t r;
    asm("mul.rn.bf16x2 %0, %1, %2;" : "=r"(r) : "r"(u), "r"(v));
    return r;
}

template <int K0>
__device__ __forceinline__ void build48(const uint32_t* xb, uint32_t ONE2, uint32_t pb) {
    constexpr int KB = (K0 / CHK) * CHK;
#define GRP(G) {                                                     \
        const uint32_t p0 = pair_val<K0 + 8 * (G) + 0>(xb, ONE2);    \
        const uint32_t p1 = pair_val<K0 + 8 * (G) + 2>(xb, ONE2);    \
        const uint32_t p2 = pair_val<K0 + 8 * (G) + 4>(xb, ONE2);    \
        const uint32_t p3 = pair_val<K0 + 8 * (G) + 6>(xb, ONE2);    \
        sts128(pb + (uint32_t)((K0 + 8 * (G) - KB) * 2), p0, p1, p2, p3); }
    GRP(0) GRP(1) GRP(2) GRP(3) GRP(4) GRP(5)
#undef GRP
}

template <int C>
__device__ __forceinline__ void build_chunk(int h, const uint32_t* xb,
                                            uint32_t ONE2, uint32_t pb) {
    if (h == 0) build48<C * CHK>(xb, ONE2, pb);
    else        build48<C * CHK + 48>(xb, ONE2, pb);
}

} // namespace

__global__ void __launch_bounds__(256, 2)
tmpnn_kernel(const float* __restrict__ X, const float* __restrict__ W,
             float* __restrict__ out)
{
    extern __shared__ char smem[];
    float*    xs  = reinterpret_cast<float*>(smem + OFF_X);     // [128][34] fp32 residual
    uint32_t* xsb = reinterpret_cast<uint32_t*>(smem + OFF_XB); // [128][20] bf16x2 copy
    uint4*    BfLo = reinterpret_cast<uint4*>(smem + OFF_BL);   // [36][32]
    uint4*    BfHi = reinterpret_cast<uint4*>(smem + OFF_BH);   // [36][32]
    const uint32_t sbase = cvta_smem(smem);
    const uint32_t pP = sbase + OFF_P;
    const uint32_t ONE2 = 0x3F803F80u;   // bf16x2 {1.0, 1.0}

    const int tid  = threadIdx.x;
    const int lane = tid & 31;
    const int w    = tid >> 5;
    const int row  = w * 16 + (lane & 15);   // warp-owned build/mma row
    const int h    = lane >> 4;              // 0: cols [0,48), 1: [48,96) of chunk

    // ---- stage X tile: fp32 + bf16x2 copies ----
    const float* Xb = X + (size_t)blockIdx.x * 4096;
    for (int i = tid; i < 4096; i += 256)
        xs[(i >> 5) * XSTR + (i & 31)] = Xb[i];
    for (int i = tid; i < 128 * 16; i += 256) {
        const int rr = i >> 4, j = i & 15;
        xsb[rr * XBSTR + j] = pack2(Xb[rr * 32 + 2 * j], Xb[rr * 32 + 2 * j + 1]);
    }

    // ---- frag-ordered symmetric-folded B tables (lane-contiguous) ----
    for (int idx = tid; idx < 2 * NKT * 32; idx += 256) {
        const int t   = idx / (NKT * 32);
        const int rem = idx - t * (NKT * 32);
        const int kt  = rem >> 5;
        const int l   = rem & 31;
        const int n0  = (l >> 2) + t * 16;
        const int kb  = kt * 16 + (l & 3) * 2;
        uint4 q;
        q.x = pack2(wv(W, kb, n0),          wv(W, kb + 1, n0));
        q.y = pack2(wv(W, kb + 8, n0),      wv(W, kb + 9, n0));
        q.z = pack2(wv(W, kb, n0 + 8),      wv(W, kb + 1, n0 + 8));
        q.w = pack2(wv(W, kb + 8, n0 + 8),  wv(W, kb + 9, n0 + 8));
        (t == 0 ? BfLo : BfHi)[rem] = q;
    }
    __syncthreads();   // the only CTA-wide barrier

    const uint32_t abase = pP + (uint32_t)row * (PSTR * 2) + (uint32_t)((lane >> 4) * 16);
    const uint32_t pbrow = pP + (uint32_t)row * (PSTR * 2);

    for (int step = 0; step < N_STEPS; ++step) {
        const bool full = (step != N_STEPS - 1);   // last step: only col 0 needed

        // bf16x2 x of this thread's row (4 x LDS.128)
        uint32_t xb[16];
        #pragma unroll
        for (int q = 0; q < 4; ++q) {
            const uint4 t4 = *reinterpret_cast<const uint4*>(&xsb[row * XBSTR + q * 4]);
            xb[4 * q] = t4.x; xb[4 * q + 1] = t4.y; xb[4 * q + 2] = t4.z; xb[4 * q + 3] = t4.w;
        }

        float acc[4][4];
        #pragma unroll
        for (int nt = 0; nt < 4; ++nt)
            #pragma unroll
            for (int i = 0; i < 4; ++i) acc[nt][i] = 0.0f;

        #pragma unroll
        for (int c = 0; c < NCH; ++c) {
            switch (c) {
                case 0: build_chunk<0>(h, xb, ONE2, pbrow); break;
                case 1: build_chunk<1>(h, xb, ONE2, pbrow); break;
                case 2: build_chunk<2>(h, xb, ONE2, pbrow); break;
                case 3: build_chunk<3>(h, xb, ONE2, pbrow); break;
                case 4: build_chunk<4>(h, xb, ONE2, pbrow); break;
                default: build_chunk<5>(h, xb, ONE2, pbrow); break;
            }
            __syncwarp();   // publish P rows to this warp's ldmatrix

            #pragma unroll
            for (int ki = 0; ki < KT_CH; ++ki) {
                uint32_t a0, a1, a2, a3;
                ldmA(a0, a1, a2, a3, abase + (uint32_t)(ki * 32));
                const int kt = c * KT_CH + ki;
                const uint4 ql = BfLo[kt * 32 + lane];
                mma16816(acc[0], a0, a1, a2, a3, ql.x, ql.y);
                mma16816(acc[1], a0, a1, a2, a3, ql.z, ql.w);
                if (full) {
                    const uint4 qh = BfHi[kt * 32 + lane];
                    mma16816(acc[2], a0, a1, a2, a3, qh.x, qh.y);
                    mma16816(acc[3], a0, a1, a2, a3, qh.z, qh.w);
                }
            }
            __syncwarp();   // mma reads done before next chunk overwrites P
        }

        // ---- epilogue: fp32 residual add, refresh bf16x2 copy ----
        {
            const int r0 = w * 16 + (lane >> 2);
            const int cb = (lane & 3) * 2;
            #pragma unroll
            for (int nt = 0; nt < 4; ++nt) {
                if (nt > 0 && !full) break;
                const int cc = nt * 8 + cb;
                float2* p0 = reinterpret_cast<float2*>(&xs[r0 * XSTR + cc]);
                float2* p1 = reinterpret_cast<float2*>(&xs[(r0 + 8) * XSTR + cc]);
                float2 v0 = *p0, v1 = *p1;
                v0.x += acc[nt][0]; v0.y += acc[nt][1];
                v1.x += acc[nt][2]; v1.y += acc[nt][3];
                *p0 = v0; *p1 = v1;
                if (full) {
                    xsb[r0 * XBSTR + (cc >> 1)]       = pack2(v0.x, v0.y);
                    xsb[(r0 + 8) * XBSTR + (cc >> 1)] = pack2(v1.x, v1.y);
                }
            }
        }
        __syncwarp();   // epilogue visible to next step's xb reload
    }

    if (h == 0)
        out[(size_t)blockIdx.x * 128 + row] = xs[row * XSTR];
}

extern "C" void kernel_launch(void* const* d_in, const int* in_sizes, int n_in,
                              void* d_out, int out_size) {
    const float* X = (const float*)d_in[0];
    const float* W = (const float*)d_in[1];
    float* out = (float*)d_out;
    const int rows = in_sizes[0] / 32;
    const int blocks = rows / 128;
    cudaFuncSetAttribute(tmpnn_kernel, cudaFuncAttributeMaxDynamicSharedMemorySize,
                         SMEM_BYTES);
    tmpnn_kernel<<<blocks, 256, SMEM_BYTES>>>(X, W, out);
}

// round 8
// speedup vs baseline: 1.9280x; 1.3179x over previous
#include <cuda_runtime.h>
#include <cuda_bf16.h>
#include <cstdint>
#include <cstddef>

// TMPNN: 7 steps of x += poly(x) @ W, M=131072, N=32, symmetric-folded K=561->576.
// R8: segment-ordered columns (broadcast-f x natural-pair operands -> ~1 HMUL2
// per column pair, PRMTs amortized), residual held in MMA accumulator registers
// (no fp32 SMEM copy, no epilogue add), 3 CTAs/SM.
// Column layout:
//   f even: body m=f..31 (len 32-f);  f odd: body m=f+1..31 (len 31-f)
//   [0,512): bodies concatenated (all even-aligned, even length)
//   [512,528): odd diagonals x_f^2, f = 1,3,...,31
//   [528,560): linear x_j;  560: bias;  [561,576): zero pad

namespace {

constexpr int N_STEPS = 7;
constexpr int NKT   = 36;            // k-tiles of 16 (K = 576)
constexpr int NCH   = 6;             // K chunks
constexpr int KT_CH = 6;             // k-tiles per chunk
constexpr int CHK   = 96;            // cols per chunk
constexpr int PSTR  = 104;           // P row stride els (208 B; ldmatrix conflict-free)
constexpr int XBSTR = 20;            // xsb row stride (uint32 bf16x2), 80 B

constexpr int OFF_XB = 0;                            // u32 xsb[128][20] = 10240
constexpr int OFF_P  = 128 * XBSTR * 4;              // 10240: bf16 P[128][104] = 26624
constexpr int OFF_BL = OFF_P + 128 * PSTR * 2;       // 36864: uint4 BfLo[36][32] = 18432
constexpr int OFF_BH = OFF_BL + NKT * 32 * 16;       // 55296: uint4 BfHi[36][32]
constexpr int SMEM_BYTES = OFF_BH + NKT * 32 * 16;   // 73728 -> 3 CTAs/SM

__device__ __forceinline__ uint32_t cvta_smem(const void* p) {
    uint32_t a;
    asm volatile("{\n\t.reg .u64 t;\n\tcvta.to.shared.u64 t, %1;\n\tcvt.u32.u64 %0, t;\n\t}"
                 : "=r"(a) : "l"(p));
    return a;
}

__device__ __forceinline__ uint32_t pack2(float lo, float hi) {
    uint32_t r;
    asm("cvt.rn.bf16x2.f32 %0, %1, %2;" : "=r"(r) : "f"(hi), "f"(lo));
    return r;
}

__device__ __forceinline__ void sts128(uint32_t a, uint32_t x, uint32_t y,
                                       uint32_t z, uint32_t w) {
    asm volatile("st.shared.v4.b32 [%0], {%1,%2,%3,%4};"
                 :: "r"(a), "r"(x), "r"(y), "r"(z), "r"(w));
}

__device__ __forceinline__ void ldmA(uint32_t& a0, uint32_t& a1, uint32_t& a2,
                                     uint32_t& a3, uint32_t addr) {
    asm volatile("ldmatrix.sync.aligned.m8n8.x4.shared.b16 {%0,%1,%2,%3}, [%4];"
                 : "=r"(a0), "=r"(a1), "=r"(a2), "=r"(a3) : "r"(addr));
}

__device__ __forceinline__ void mma16816(float* c, uint32_t a0, uint32_t a1,
                                         uint32_t a2, uint32_t a3,
                                         uint32_t b0, uint32_t b1) {
    asm volatile("mma.sync.aligned.m16n8k16.row.col.f32.bf16.bf16.f32 "
                 "{%0,%1,%2,%3}, {%4,%5,%6,%7}, {%8,%9}, {%0,%1,%2,%3};"
                 : "+f"(c[0]), "+f"(c[1]), "+f"(c[2]), "+f"(c[3])
                 : "r"(a0), "r"(a1), "r"(a2), "r"(a3), "r"(b0), "r"(b1));
}

// ---- column maps (compile-time for build, runtime for B init) ----
__host__ __device__ constexpr int blen(int f) { return (f & 1) ? 31 - f : 32 - f; }
__host__ __device__ constexpr int sstart(int f) {
    int s = 0;
    for (int g = 0; g < f; ++g) s += blen(g);
    return s;
}
__host__ __device__ constexpr int segf(int k) {    // k < 512
    int f = 0;
    while (f < 31 && sstart(f + 1) <= k) ++f;
    return f;
}
__host__ __device__ constexpr int colm(int k) {    // k < 512
    const int f = segf(k);
    return (((f & 1) ? f + 1 : f)) + (k - sstart(f));
}

// per-half operand maps: reg 0..15 = xb[reg]; 16 = 1.0; 17 = 0.0
__host__ __device__ constexpr int uR(int k) {
    return (k < 512) ? (segf(k) >> 1)
         : (k < 528) ? (k - 512)
         : (k < 560) ? ((k - 528) >> 1)
         : (k == 560) ? 16 : 17;
}
__host__ __device__ constexpr int uH(int k) {
    return (k < 512) ? (segf(k) & 1) : (k < 528) ? 1 : (k < 560) ? ((k - 528) & 1) : 0;
}
__host__ __device__ constexpr int vR(int k) {
    return (k < 512) ? (colm(k) >> 1)
         : (k < 528) ? (k - 512)
         : (k <= 560) ? 16 : 17;
}
__host__ __device__ constexpr int vH(int k) {
    return (k < 512) ? (colm(k) & 1) : (k < 528) ? 1 : 0;
}

// Combine two bf16 halves into one bf16x2 register.
template <int R0, int H0, int R1, int H1>
__device__ __forceinline__ uint32_t comb(const uint32_t* xb) {
    if (R0 >= 16 && R1 >= 16)    // fully constant
        return (uint32_t)((R0 == 16 ? 0x3F80u : 0u) | ((R1 == 16 ? 0x3F80u : 0u) << 16));
    const uint32_t s0 = (R0 >= 16) ? ((R0 == 16) ? 0x3F803F80u : 0u) : xb[(R0 < 16) ? R0 : 0];
    const uint32_t s1 = (R1 >= 16) ? ((R1 == 16) ? 0x3F803F80u : 0u) : xb[(R1 < 16) ? R1 : 0];
    if (R0 == R1 && H0 == 0 && H1 == 1) return s0;   // natural pair: free
    const int sel = (H0 ? 0x32 : 0x10) | ((H1 ? 0x76 : 0x54) << 8);
    return __byte_perm(s0, s1, sel);                  // broadcast / splice (CSE'd)
}

// bf16x2 value of columns {A, A+1}.
template <int A>
__device__ __forceinline__ uint32_t pair_val(const uint32_t* xb) {
    if (A == 560) return 0x00003F80u;   // {bias=1, pad=0}
    if (A >= 562) return 0u;            // pad
    const uint32_t u = comb<uR(A), uH(A), uR(A + 1), uH(A + 1)>(xb);
    const uint32_t v = comb<vR(A), vH(A), vR(A + 1), vH(A + 1)>(xb);
    uint32_t r;
    asm("mul.rn.bf16x2 %0, %1, %2;" : "=r"(r) : "r"(u), "r"(v));
    return r;
}

template <int K0>
__device__ __forceinline__ void build48(const uint32_t* xb, uint32_t pb) {
    constexpr int KB = (K0 / CHK) * CHK;
#define GRP(G) {                                               \
        const uint32_t p0 = pair_val<K0 + 8 * (G) + 0>(xb);    \
        const uint32_t p1 = pair_val<K0 + 8 * (G) + 2>(xb);    \
        const uint32_t p2 = pair_val<K0 + 8 * (G) + 4>(xb);    \
        const uint32_t p3 = pair_val<K0 + 8 * (G) + 6>(xb);    \
        sts128(pb + (uint32_t)((K0 + 8 * (G) - KB) * 2), p0, p1, p2, p3); }
    GRP(0) GRP(1) GRP(2) GRP(3) GRP(4) GRP(5)
#undef GRP
}

template <int C>
__device__ __forceinline__ void build_chunk(int h, const uint32_t* xb, uint32_t pb) {
    if (h == 0) build48<C * CHK>(xb, pb);
    else        build48<C * CHK + 48>(xb, pb);
}

// ---- runtime (f, m) for B-table init ----
__device__ void colfm_rt(int k, int& f, int& m) {
    if (k < 512) {
        int ff = 0, s = 0;
        #pragma unroll 1
        while (ff < 31) {
            const int bl = (ff & 1) ? 31 - ff : 32 - ff;
            if (s + bl > k) break;
            s += bl; ++ff;
        }
        f = ff;
        m = (((ff & 1) ? ff + 1 : ff)) + (k - s);
    } else {
        f = 2 * (k - 512) + 1;
        m = f;
    }
}

__device__ float wv(const float* __restrict__ W, int k, int n) {
    if (k < 528) {
        int f, m;
        colfm_rt(k, f, m);
        float w = __ldg(&W[(33 + f * 32 + m) * 32 + n]);
        if (m != f) w += __ldg(&W[(33 + m * 32 + f) * 32 + n]);
        return w;
    }
    if (k < 560) return __ldg(&W[(1 + (k - 528)) * 32 + n]);
    if (k == 560) return __ldg(&W[n]);
    return 0.0f;
}

} // namespace

__global__ void __launch_bounds__(256, 3)
tmpnn_kernel(const float* __restrict__ X, const float* __restrict__ W,
             float* __restrict__ out)
{
    extern __shared__ char smem[];
    uint32_t* xsb  = reinterpret_cast<uint32_t*>(smem + OFF_XB); // [128][20] bf16x2
    uint4*    BfLo = reinterpret_cast<uint4*>(smem + OFF_BL);    // [36][32]
    uint4*    BfHi = reinterpret_cast<uint4*>(smem + OFF_BH);    // [36][32]
    const uint32_t sbase = cvta_smem(smem);
    const uint32_t pP = sbase + OFF_P;

    const int tid  = threadIdx.x;
    const int lane = tid & 31;
    const int w    = tid >> 5;
    const int row  = w * 16 + (lane & 15);   // warp-owned build/mma row
    const int h    = lane >> 4;              // 0: cols [0,48), 1: [48,96) of chunk
    const int r0   = w * 16 + (lane >> 2);   // mma-accumulator row (and r0+8)
    const int cb   = (lane & 3) * 2;         // mma-accumulator col base

    // ---- stage bf16x2 X copy ----
    const float* Xb = X + (size_t)blockIdx.x * 4096;
    for (int i = tid; i < 128 * 16; i += 256) {
        const int rr = i >> 4, j = i & 15;
        const float2 v = __ldg(reinterpret_cast<const float2*>(Xb + rr * 32 + 2 * j));
        xsb[rr * XBSTR + j] = pack2(v.x, v.y);
    }

    // ---- fp32 residual in mma-accumulator layout ----
    float res[4][4];
    #pragma unroll
    for (int nt = 0; nt < 4; ++nt) {
        const int cc = nt * 8 + cb;
        const float2 v0 = __ldg(reinterpret_cast<const float2*>(Xb + r0 * 32 + cc));
        const float2 v1 = __ldg(reinterpret_cast<const float2*>(Xb + (r0 + 8) * 32 + cc));
        res[nt][0] = v0.x; res[nt][1] = v0.y;
        res[nt][2] = v1.x; res[nt][3] = v1.y;
    }

    // ---- frag-ordered symmetric-folded B tables ----
    for (int idx = tid; idx < 2 * NKT * 32; idx += 256) {
        const int t   = idx / (NKT * 32);
        const int rem = idx - t * (NKT * 32);
        const int kt  = rem >> 5;
        const int l   = rem & 31;
        const int n0  = (l >> 2) + t * 16;
        const int kb  = kt * 16 + (l & 3) * 2;
        uint4 q;
        q.x = pack2(wv(W, kb, n0),          wv(W, kb + 1, n0));
        q.y = pack2(wv(W, kb + 8, n0),      wv(W, kb + 9, n0));
        q.z = pack2(wv(W, kb, n0 + 8),      wv(W, kb + 1, n0 + 8));
        q.w = pack2(wv(W, kb + 8, n0 + 8),  wv(W, kb + 9, n0 + 8));
        (t == 0 ? BfLo : BfHi)[rem] = q;
    }
    __syncthreads();   // the only CTA-wide barrier

    const uint32_t abase = pP + (uint32_t)row * (PSTR * 2) + (uint32_t)((lane >> 4) * 16);
    const uint32_t pbrow = pP + (uint32_t)row * (PSTR * 2);

    for (int step = 0; step < N_STEPS; ++step) {
        const bool full = (step != N_STEPS - 1);   // last step: only output col 0

        // bf16x2 x of this thread's build row (4 x LDS.128)
        uint32_t xb[16];
        #pragma unroll
        for (int q = 0; q < 4; ++q) {
            const uint4 t4 = *reinterpret_cast<const uint4*>(&xsb[row * XBSTR + q * 4]);
            xb[4 * q] = t4.x; xb[4 * q + 1] = t4.y; xb[4 * q + 2] = t4.z; xb[4 * q + 3] = t4.w;
        }

        #pragma unroll
        for (int c = 0; c < NCH; ++c) {
            switch (c) {
                case 0: build_chunk<0>(h, xb, pbrow); break;
                case 1: build_chunk<1>(h, xb, pbrow); break;
                case 2: build_chunk<2>(h, xb, pbrow); break;
                case 3: build_chunk<3>(h, xb, pbrow); break;
                case 4: build_chunk<4>(h, xb, pbrow); break;
                default: build_chunk<5>(h, xb, pbrow); break;
            }
            __syncwarp();   // publish P rows to this warp's ldmatrix

            #pragma unroll
            for (int ki = 0; ki < KT_CH; ++ki) {
                uint32_t a0, a1, a2, a3;
                ldmA(a0, a1, a2, a3, abase + (uint32_t)(ki * 32));
                const int kt = c * KT_CH + ki;
                const uint4 ql = BfLo[kt * 32 + lane];
                mma16816(res[0], a0, a1, a2, a3, ql.x, ql.y);
                if (full) {
                    mma16816(res[1], a0, a1, a2, a3, ql.z, ql.w);
                    const uint4 qh = BfHi[kt * 32 + lane];
                    mma16816(res[2], a0, a1, a2, a3, qh.x, qh.y);
                    mma16816(res[3], a0, a1, a2, a3, qh.z, qh.w);
                }
            }
            __syncwarp();   // mma reads done before next chunk overwrites P
        }

        // ---- epilogue: refresh bf16x2 copy from accumulator registers ----
        if (full) {
            #pragma unroll
            for (int nt = 0; nt < 4; ++nt) {
                const int cc = nt * 8 + cb;
                xsb[r0 * XBSTR + (cc >> 1)]       = pack2(res[nt][0], res[nt][1]);
                xsb[(r0 + 8) * XBSTR + (cc >> 1)] = pack2(res[nt][2], res[nt][3]);
            }
            __syncwarp();   // visible to next step's xb reload
        }
    }

    if ((lane & 3) == 0) {
        out[(size_t)blockIdx.x * 128 + r0]     = res[0][0];
        out[(size_t)blockIdx.x * 128 + r0 + 8] = res[0][2];
    }
}

extern "C" void kernel_launch(void* const* d_in, const int* in_sizes, int n_in,
                              void* d_out, int out_size) {
    const float* X = (const float*)d_in[0];
    const float* W = (const float*)d_in[1];
    float* out = (float*)d_out;
    const int rows = in_sizes[0] / 32;
    const int blocks = rows / 128;
    cudaFuncSetAttribute(tmpnn_kernel, cudaFuncAttributeMaxDynamicSharedMemorySize,
                         SMEM_BYTES);
    tmpnn_kernel<<<blocks, 256, SMEM_BYTES>>>(X, W, out);
}

// round 9
// speedup vs baseline: 3.2175x; 1.6688x over previous
#include <cuda_runtime.h>
#include <cuda_bf16.h>
#include <cstdint>
#include <cstddef>

// TMPNN: 7 steps of x += poly(x) @ W, M=131072, N=32, symmetric-folded K=561->576.
// R9: B-fragment tables moved to __device__ global scratch (identical across
// CTAs, L2/L1-shared; written once by an init kernel) -> SMEM 73.7KB -> 36.9KB
// -> 4 CTAs/SM. Everything else as R8: segment-ordered columns, HMUL2 build,
// residual in MMA accumulators, warp-autonomous steps, last-step N-thinning.

namespace {

constexpr int N_STEPS = 7;
constexpr int NKT   = 36;            // k-tiles of 16 (K = 576)
constexpr int NCH   = 6;             // K chunks
constexpr int KT_CH = 6;             // k-tiles per chunk
constexpr int CHK   = 96;            // cols per chunk
constexpr int PSTR  = 104;           // P row stride els (208 B; ldmatrix conflict-free)
constexpr int XBSTR = 20;            // xsb row stride (uint32 bf16x2), 80 B

constexpr int OFF_XB = 0;                            // u32 xsb[128][20] = 10240
constexpr int OFF_P  = 128 * XBSTR * 4;              // 10240: bf16 P[128][104] = 26624
constexpr int SMEM_BYTES = OFF_P + 128 * PSTR * 2;   // 36864 -> 4 CTAs/SM

__device__ __forceinline__ uint32_t cvta_smem(const void* p) {
    uint32_t a;
    asm volatile("{\n\t.reg .u64 t;\n\tcvta.to.shared.u64 t, %1;\n\tcvt.u32.u64 %0, t;\n\t}"
                 : "=r"(a) : "l"(p));
    return a;
}

__device__ __forceinline__ uint32_t pack2(float lo, float hi) {
    uint32_t r;
    asm("cvt.rn.bf16x2.f32 %0, %1, %2;" : "=r"(r) : "f"(hi), "f"(lo));
    return r;
}

__device__ __forceinline__ void sts128(uint32_t a, uint32_t x, uint32_t y,
                                       uint32_t z, uint32_t w) {
    asm volatile("st.shared.v4.b32 [%0], {%1,%2,%3,%4};"
                 :: "r"(a), "r"(x), "r"(y), "r"(z), "r"(w));
}

__device__ __forceinline__ void ldmA(uint32_t& a0, uint32_t& a1, uint32_t& a2,
                                     uint32_t& a3, uint32_t addr) {
    asm volatile("ldmatrix.sync.aligned.m8n8.x4.shared.b16 {%0,%1,%2,%3}, [%4];"
                 : "=r"(a0), "=r"(a1), "=r"(a2), "=r"(a3) : "r"(addr));
}

__device__ __forceinline__ void mma16816(float* c, uint32_t a0, uint32_t a1,
                                         uint32_t a2, uint32_t a3,
                                         uint32_t b0, uint32_t b1) {
    asm volatile("mma.sync.aligned.m16n8k16.row.col.f32.bf16.bf16.f32 "
                 "{%0,%1,%2,%3}, {%4,%5,%6,%7}, {%8,%9}, {%0,%1,%2,%3};"
                 : "+f"(c[0]), "+f"(c[1]), "+f"(c[2]), "+f"(c[3])
                 : "r"(a0), "r"(a1), "r"(a2), "r"(a3), "r"(b0), "r"(b1));
}

// ---- column maps (compile-time for build, runtime for B init) ----
// Layout: [0,512) per-f bodies (f even: m=f..31; f odd: m=f+1..31),
// [512,528) odd diagonals, [528,560) linear, 560 bias, [561,576) pad.
__host__ __device__ constexpr int blen(int f) { return (f & 1) ? 31 - f : 32 - f; }
__host__ __device__ constexpr int sstart(int f) {
    int s = 0;
    for (int g = 0; g < f; ++g) s += blen(g);
    return s;
}
__host__ __device__ constexpr int segf(int k) {    // k < 512
    int f = 0;
    while (f < 31 && sstart(f + 1) <= k) ++f;
    return f;
}
__host__ __device__ constexpr int colm(int k) {    // k < 512
    const int f = segf(k);
    return (((f & 1) ? f + 1 : f)) + (k - sstart(f));
}

// per-half operand maps: reg 0..15 = xb[reg]; 16 = 1.0; 17 = 0.0
__host__ __device__ constexpr int uR(int k) {
    return (k < 512) ? (segf(k) >> 1)
         : (k < 528) ? (k - 512)
         : (k < 560) ? ((k - 528) >> 1)
         : (k == 560) ? 16 : 17;
}
__host__ __device__ constexpr int uH(int k) {
    return (k < 512) ? (segf(k) & 1) : (k < 528) ? 1 : (k < 560) ? ((k - 528) & 1) : 0;
}
__host__ __device__ constexpr int vR(int k) {
    return (k < 512) ? (colm(k) >> 1)
         : (k < 528) ? (k - 512)
         : (k <= 560) ? 16 : 17;
}
__host__ __device__ constexpr int vH(int k) {
    return (k < 512) ? (colm(k) & 1) : (k < 528) ? 1 : 0;
}

template <int R0, int H0, int R1, int H1>
__device__ __forceinline__ uint32_t comb(const uint32_t* xb) {
    if (R0 >= 16 && R1 >= 16)
        return (uint32_t)((R0 == 16 ? 0x3F80u : 0u) | ((R1 == 16 ? 0x3F80u : 0u) << 16));
    const uint32_t s0 = (R0 >= 16) ? ((R0 == 16) ? 0x3F803F80u : 0u) : xb[(R0 < 16) ? R0 : 0];
    const uint32_t s1 = (R1 >= 16) ? ((R1 == 16) ? 0x3F803F80u : 0u) : xb[(R1 < 16) ? R1 : 0];
    if (R0 == R1 && H0 == 0 && H1 == 1) return s0;   // natural pair: free
    const int sel = (H0 ? 0x32 : 0x10) | ((H1 ? 0x76 : 0x54) << 8);
    return __byte_perm(s0, s1, sel);                  // broadcast/splice (CSE'd)
}

template <int A>
__device__ __forceinline__ uint32_t pair_val(const uint32_t* xb) {
    if (A == 560) return 0x00003F80u;   // {bias=1, pad=0}
    if (A >= 562) return 0u;            // pad
    const uint32_t u = comb<uR(A), uH(A), uR(A + 1), uH(A + 1)>(xb);
    const uint32_t v = comb<vR(A), vH(A), vR(A + 1), vH(A + 1)>(xb);
    uint32_t r;
    asm("mul.rn.bf16x2 %0, %1, %2;" : "=r"(r) : "r"(u), "r"(v));
    return r;
}

template <int K0>
__device__ __forceinline__ void build48(const uint32_t* xb, uint32_t pb) {
    constexpr int KB = (K0 / CHK) * CHK;
#define GRP(G) {                                               \
        const uint32_t p0 = pair_val<K0 + 8 * (G) + 0>(xb);    \
        const uint32_t p1 = pair_val<K0 + 8 * (G) + 2>(xb);    \
        const uint32_t p2 = pair_val<K0 + 8 * (G) + 4>(xb);    \
        const uint32_t p3 = pair_val<K0 + 8 * (G) + 6>(xb);    \
        sts128(pb + (uint32_t)((K0 + 8 * (G) - KB) * 2), p0, p1, p2, p3); }
    GRP(0) GRP(1) GRP(2) GRP(3) GRP(4) GRP(5)
#undef GRP
}

template <int C>
__device__ __forceinline__ void build_chunk(int h, const uint32_t* xb, uint32_t pb) {
    if (h == 0) build48<C * CHK>(xb, pb);
    else        build48<C * CHK + 48>(xb, pb);
}

// ---- runtime (f, m) for B-table init ----
__device__ void colfm_rt(int k, int& f, int& m) {
    if (k < 512) {
        int ff = 0, s = 0;
        #pragma unroll 1
        while (ff < 31) {
            const int bl = (ff & 1) ? 31 - ff : 32 - ff;
            if (s + bl > k) break;
            s += bl; ++ff;
        }
        f = ff;
        m = (((ff & 1) ? ff + 1 : ff)) + (k - s);
    } else {
        f = 2 * (k - 512) + 1;
        m = f;
    }
}

__device__ float wv(const float* __restrict__ W, int k, int n) {
    if (k < 528) {
        int f, m;
        colfm_rt(k, f, m);
        float w = __ldg(&W[(33 + f * 32 + m) * 32 + n]);
        if (m != f) w += __ldg(&W[(33 + m * 32 + f) * 32 + n]);
        return w;
    }
    if (k < 560) return __ldg(&W[(1 + (k - 528)) * 32 + n]);
    if (k == 560) return __ldg(&W[n]);
    return 0.0f;
}

} // namespace

// B-fragment tables, identical for every CTA: [0,1152) = Lo (n 0..15),
// [1152,2304) = Hi (n 16..31). Written by bf_init, read via __ldg.
__device__ uint4 g_Bf[2 * NKT * 32];

__global__ void bf_init_kernel(const float* __restrict__ W) {
    const int idx = blockIdx.x * blockDim.x + threadIdx.x;
    if (idx >= 2 * NKT * 32) return;
    const int t   = idx / (NKT * 32);
    const int rem = idx - t * (NKT * 32);
    const int kt  = rem >> 5;
    const int l   = rem & 31;
    const int n0  = (l >> 2) + t * 16;
    const int kb  = kt * 16 + (l & 3) * 2;
    uint4 q;
    q.x = pack2(wv(W, kb, n0),          wv(W, kb + 1, n0));
    q.y = pack2(wv(W, kb + 8, n0),      wv(W, kb + 9, n0));
    q.z = pack2(wv(W, kb, n0 + 8),      wv(W, kb + 1, n0 + 8));
    q.w = pack2(wv(W, kb + 8, n0 + 8),  wv(W, kb + 9, n0 + 8));
    g_Bf[idx] = q;
}

__global__ void __launch_bounds__(256, 4)
tmpnn_kernel(const float* __restrict__ X, float* __restrict__ out)
{
    extern __shared__ char smem[];
    uint32_t* xsb = reinterpret_cast<uint32_t*>(smem + OFF_XB); // [128][20] bf16x2
    const uint32_t sbase = cvta_smem(smem);
    const uint32_t pP = sbase + OFF_P;

    const int tid  = threadIdx.x;
    const int lane = tid & 31;
    const int w    = tid >> 5;
    const int row  = w * 16 + (lane & 15);   // warp-owned build/mma row
    const int h    = lane >> 4;              // 0: cols [0,48), 1: [48,96) of chunk
    const int r0   = w * 16 + (lane >> 2);   // mma-accumulator row (and r0+8)
    const int cb   = (lane & 3) * 2;         // mma-accumulator col base

    // ---- stage bf16x2 X copy ----
    const float* Xb = X + (size_t)blockIdx.x * 4096;
    for (int i = tid; i < 128 * 16; i += 256) {
        const int rr = i >> 4, j = i & 15;
        const float2 v = __ldg(reinterpret_cast<const float2*>(Xb + rr * 32 + 2 * j));
        xsb[rr * XBSTR + j] = pack2(v.x, v.y);
    }

    // ---- fp32 residual in mma-accumulator layout ----
    float res[4][4];
    #pragma unroll
    for (int nt = 0; nt < 4; ++nt) {
        const int cc = nt * 8 + cb;
        const float2 v0 = __ldg(reinterpret_cast<const float2*>(Xb + r0 * 32 + cc));
        const float2 v1 = __ldg(reinterpret_cast<const float2*>(Xb + (r0 + 8) * 32 + cc));
        res[nt][0] = v0.x; res[nt][1] = v0.y;
        res[nt][2] = v1.x; res[nt][3] = v1.y;
    }
    __syncthreads();   // xsb visible CTA-wide (only barrier)

    const uint4* BfL = g_Bf + lane;
    const uint4* BfH = g_Bf + (NKT * 32) + lane;
    const uint32_t abase = pP + (uint32_t)row * (PSTR * 2) + (uint32_t)((lane >> 4) * 16);
    const uint32_t pbrow = pP + (uint32_t)row * (PSTR * 2);

    for (int step = 0; step < N_STEPS; ++step) {
        const bool full = (step != N_STEPS - 1);   // last step: only output col 0

        uint32_t xb[16];
        #pragma unroll
        for (int q = 0; q < 4; ++q) {
            const uint4 t4 = *reinterpret_cast<const uint4*>(&xsb[row * XBSTR + q * 4]);
            xb[4 * q] = t4.x; xb[4 * q + 1] = t4.y; xb[4 * q + 2] = t4.z; xb[4 * q + 3] = t4.w;
        }

        #pragma unroll
        for (int c = 0; c < NCH; ++c) {
            switch (c) {
                case 0: build_chunk<0>(h, xb, pbrow); break;
                case 1: build_chunk<1>(h, xb, pbrow); break;
                case 2: build_chunk<2>(h, xb, pbrow); break;
                case 3: build_chunk<3>(h, xb, pbrow); break;
                case 4: build_chunk<4>(h, xb, pbrow); break;
                default: build_chunk<5>(h, xb, pbrow); break;
            }
            __syncwarp();   // publish P rows to this warp's ldmatrix

            #pragma unroll
            for (int ki = 0; ki < KT_CH; ++ki) {
                uint32_t a0, a1, a2, a3;
                ldmA(a0, a1, a2, a3, abase + (uint32_t)(ki * 32));
                const int kt = c * KT_CH + ki;
                const uint4 ql = __ldg(BfL + kt * 32);
                mma16816(res[0], a0, a1, a2, a3, ql.x, ql.y);
                if (full) {
                    mma16816(res[1], a0, a1, a2, a3, ql.z, ql.w);
                    const uint4 qh = __ldg(BfH + kt * 32);
                    mma16816(res[2], a0, a1, a2, a3, qh.x, qh.y);
                    mma16816(res[3], a0, a1, a2, a3, qh.z, qh.w);
                }
            }
            __syncwarp();   // mma reads done before next chunk overwrites P
        }

        // ---- epilogue: refresh bf16x2 copy from accumulator registers ----
        if (full) {
            #pragma unroll
            for (int nt = 0; nt < 4; ++nt) {
                const int cc = nt * 8 + cb;
                xsb[r0 * XBSTR + (cc >> 1)]       = pack2(res[nt][0], res[nt][1]);
                xsb[(r0 + 8) * XBSTR + (cc >> 1)] = pack2(res[nt][2], res[nt][3]);
            }
            __syncwarp();   // visible to next step's xb reload
        }
    }

    if ((lane & 3) == 0) {
        out[(size_t)blockIdx.x * 128 + r0]     = res[0][0];
        out[(size_t)blockIdx.x * 128 + r0 + 8] = res[0][2];
    }
}

extern "C" void kernel_launch(void* const* d_in, const int* in_sizes, int n_in,
                              void* d_out, int out_size) {
    const float* X = (const float*)d_in[0];
    const float* W = (const float*)d_in[1];
    float* out = (float*)d_out;
    const int rows = in_sizes[0] / 32;
    const int blocks = rows / 128;
    bf_init_kernel<<<(2 * NKT * 32 + 255) / 256, 256>>>(W);
    cudaFuncSetAttribute(tmpnn_kernel, cudaFuncAttributeMaxDynamicSharedMemorySize,
                         SMEM_BYTES);
    tmpnn_kernel<<<blocks, 256, SMEM_BYTES>>>(X, out);
}